// round 1
// baseline (speedup 1.0000x reference)
#include <cuda_runtime.h>
#include <cuda_bf16.h>
#include <cstdint>

// Problem constants
#define B_TOT   2048
#define N_TOK   98
#define C_DIM   256
#define H_NUM   8
#define HD      32
#define NW      512
#define M_ROWS  (B_TOT * N_TOK)          // 200704
#define QKV_N   (3 * C_DIM)              // 768

// -------- scratch (static device globals: no runtime allocation) --------
__device__ float g_qkv[(size_t)M_ROWS * QKV_N];   // ~616 MB
__device__ float g_att[(size_t)M_ROWS * C_DIM];   // ~205 MB
__device__ float g_bias[H_NUM * N_TOK * N_TOK];   // 8*98*98

// ---------------------------------------------------------------
// Kernel 1: gather relative-position bias  -> g_bias[h][n][m]
// ---------------------------------------------------------------
__global__ void gather_bias_kernel(const float* __restrict__ table,
                                   const int* __restrict__ rel) {
    int idx = blockIdx.x * blockDim.x + threadIdx.x;
    const int total = H_NUM * N_TOK * N_TOK;
    if (idx < total) {
        int h  = idx / (N_TOK * N_TOK);
        int nm = idx % (N_TOK * N_TOK);
        g_bias[idx] = table[rel[nm] * H_NUM + h];
    }
}

// ---------------------------------------------------------------
// SGEMM body: C[m][n] = sum_k A[m][k] * W[n][k] + bias[n]
// BM=BN=128, BK=8, TM=TN=8, 256 threads. M,N,K multiples of tile.
// ---------------------------------------------------------------
__device__ __forceinline__ void sgemm_body(const float* __restrict__ A,
                                           const float* __restrict__ W,
                                           const float* __restrict__ bias,
                                           float* __restrict__ C,
                                           int N, int K) {
    constexpr int BM = 128, BN = 128, BK = 8, TM = 8, TN = 8;
    __shared__ float As[BK][BM];
    __shared__ float Bs[BK][BN];

    const int tid  = threadIdx.x;
    const int bm0  = blockIdx.y * BM;
    const int bn0  = blockIdx.x * BN;
    const int tRow = tid >> 4;   // 0..15
    const int tCol = tid & 15;   // 0..15

    const int lRow = tid >> 1;         // 0..127
    const int lCol = (tid & 1) * 4;    // 0 or 4

    const float* Aptr = A + (size_t)(bm0 + lRow) * K + lCol;
    const float* Wptr = W + (size_t)(bn0 + lRow) * K + lCol;

    float acc[TM][TN];
#pragma unroll
    for (int i = 0; i < TM; i++)
#pragma unroll
        for (int j = 0; j < TN; j++) acc[i][j] = 0.f;

    for (int k0 = 0; k0 < K; k0 += BK) {
        float4 a4 = *reinterpret_cast<const float4*>(Aptr + k0);
        float4 w4 = *reinterpret_cast<const float4*>(Wptr + k0);
        As[lCol + 0][lRow] = a4.x; As[lCol + 1][lRow] = a4.y;
        As[lCol + 2][lRow] = a4.z; As[lCol + 3][lRow] = a4.w;
        Bs[lCol + 0][lRow] = w4.x; Bs[lCol + 1][lRow] = w4.y;
        Bs[lCol + 2][lRow] = w4.z; Bs[lCol + 3][lRow] = w4.w;
        __syncthreads();

#pragma unroll
        for (int k = 0; k < BK; k++) {
            float rm[TM], rn[TN];
            float4 m0 = *reinterpret_cast<const float4*>(&As[k][tRow * TM]);
            float4 m1 = *reinterpret_cast<const float4*>(&As[k][tRow * TM + 4]);
            float4 n0 = *reinterpret_cast<const float4*>(&Bs[k][tCol * TN]);
            float4 n1 = *reinterpret_cast<const float4*>(&Bs[k][tCol * TN + 4]);
            rm[0]=m0.x; rm[1]=m0.y; rm[2]=m0.z; rm[3]=m0.w;
            rm[4]=m1.x; rm[5]=m1.y; rm[6]=m1.z; rm[7]=m1.w;
            rn[0]=n0.x; rn[1]=n0.y; rn[2]=n0.z; rn[3]=n0.w;
            rn[4]=n1.x; rn[5]=n1.y; rn[6]=n1.z; rn[7]=n1.w;
#pragma unroll
            for (int i = 0; i < TM; i++)
#pragma unroll
                for (int j = 0; j < TN; j++)
                    acc[i][j] += rm[i] * rn[j];
        }
        __syncthreads();
    }

#pragma unroll
    for (int i = 0; i < TM; i++) {
        size_t row = (size_t)(bm0 + tRow * TM + i) * N;
#pragma unroll
        for (int j = 0; j < TN; j += 4) {
            int col = bn0 + tCol * TN + j;
            float4 o;
            o.x = acc[i][j + 0] + bias[col + 0];
            o.y = acc[i][j + 1] + bias[col + 1];
            o.z = acc[i][j + 2] + bias[col + 2];
            o.w = acc[i][j + 3] + bias[col + 3];
            *reinterpret_cast<float4*>(C + row + col) = o;
        }
    }
}

__global__ void __launch_bounds__(256)
qkv_gemm_kernel(const float* __restrict__ x,
                const float* __restrict__ w,
                const float* __restrict__ b) {
    sgemm_body(x, w, b, g_qkv, QKV_N, C_DIM);
}

__global__ void __launch_bounds__(256)
proj_gemm_kernel(const float* __restrict__ w,
                 const float* __restrict__ b,
                 float* __restrict__ out) {
    sgemm_body(g_att, w, b, out, C_DIM, C_DIM);
}

// ---------------------------------------------------------------
// Kernel 3: fused attention per (b, h).
// S = (q*scale) k^T + bias + mask ; softmax ; O = P v
// 256 threads; padded 112x112 register tiling (16x16 threads, 7x7 micro).
// ---------------------------------------------------------------
#define QROW 33    // padded row stride for q/k/v in smem
#define SROW 99    // padded row stride for S
#define PADN 112

__global__ void __launch_bounds__(256)
attn_kernel(const float* __restrict__ mask) {
    extern __shared__ float sm[];
    float* q_s = sm;                      // 112*33
    float* k_s = q_s + PADN * QROW;       // 112*33
    float* v_s = k_s + PADN * QROW;       // 112*33
    float* S   = v_s + PADN * QROW;       // 112*99

    const int tid = threadIdx.x;
    const int bh  = blockIdx.x;
    const int b   = bh >> 3;
    const int h   = bh & 7;
    const float scale = 0.17677669529663687f;   // 1/sqrt(32)

    // load q (pre-scaled), k, v ; zero the pad rows
    for (int idx = tid; idx < PADN * HD; idx += 256) {
        int n = idx >> 5, d = idx & 31;
        float qv = 0.f, kv = 0.f, vv = 0.f;
        if (n < N_TOK) {
            size_t base = ((size_t)(b * N_TOK + n)) * QKV_N + h * HD + d;
            qv = g_qkv[base] * scale;
            kv = g_qkv[base + C_DIM];
            vv = g_qkv[base + 2 * C_DIM];
        }
        q_s[n * QROW + d] = qv;
        k_s[n * QROW + d] = kv;
        v_s[n * QROW + d] = vv;
    }
    __syncthreads();

    const int tx = tid & 15, ty = tid >> 4;

    // ---- S = q k^T ----
    float acc[7][7];
#pragma unroll
    for (int i = 0; i < 7; i++)
#pragma unroll
        for (int j = 0; j < 7; j++) acc[i][j] = 0.f;

#pragma unroll 4
    for (int kk = 0; kk < HD; kk++) {
        float af[7], bf[7];
#pragma unroll
        for (int ii = 0; ii < 7; ii++) af[ii] = q_s[(ty + 16 * ii) * QROW + kk];
#pragma unroll
        for (int jj = 0; jj < 7; jj++) bf[jj] = k_s[(tx + 16 * jj) * QROW + kk];
#pragma unroll
        for (int ii = 0; ii < 7; ii++)
#pragma unroll
            for (int jj = 0; jj < 7; jj++)
                acc[ii][jj] += af[ii] * bf[jj];
    }

    const float* mp = mask + (size_t)(b & (NW - 1)) * (N_TOK * N_TOK);
    const float* bp = g_bias + (size_t)h * (N_TOK * N_TOK);
#pragma unroll
    for (int ii = 0; ii < 7; ii++) {
        int i = ty + 16 * ii;
#pragma unroll
        for (int jj = 0; jj < 7; jj++) {
            int j = tx + 16 * jj;
            if (j < N_TOK)
                S[i * SROW + j] = (i < N_TOK)
                    ? acc[ii][jj] + bp[i * N_TOK + j] + mp[i * N_TOK + j]
                    : 0.f;
        }
    }
    __syncthreads();

    // ---- row softmax (one warp per row, strided) ----
    {
        const int lane = tid & 31, wp = tid >> 5;
        for (int i = wp; i < N_TOK; i += 8) {
            float* row = S + i * SROW;
            float m = -1e30f;
            for (int j = lane; j < N_TOK; j += 32) m = fmaxf(m, row[j]);
#pragma unroll
            for (int off = 16; off; off >>= 1)
                m = fmaxf(m, __shfl_xor_sync(0xFFFFFFFFu, m, off));
            float s = 0.f;
            for (int j = lane; j < N_TOK; j += 32) {
                float e = __expf(row[j] - m);
                row[j] = e;
                s += e;
            }
#pragma unroll
            for (int off = 16; off; off >>= 1)
                s += __shfl_xor_sync(0xFFFFFFFFu, s, off);
            float inv = 1.f / s;
            for (int j = lane; j < N_TOK; j += 32) row[j] *= inv;
        }
    }
    __syncthreads();

    // ---- O = P v  (112x32 tile: each thread 7 rows x 2 cols) ----
    float oacc[7][2];
#pragma unroll
    for (int i = 0; i < 7; i++) { oacc[i][0] = 0.f; oacc[i][1] = 0.f; }

#pragma unroll 2
    for (int kk = 0; kk < N_TOK; kk++) {
        float vf0 = v_s[kk * QROW + tx];
        float vf1 = v_s[kk * QROW + tx + 16];
#pragma unroll
        for (int ii = 0; ii < 7; ii++) {
            float p = S[(ty + 16 * ii) * SROW + kk];
            oacc[ii][0] += p * vf0;
            oacc[ii][1] += p * vf1;
        }
    }

#pragma unroll
    for (int ii = 0; ii < 7; ii++) {
        int i = ty + 16 * ii;
        if (i < N_TOK) {
            size_t o = ((size_t)(b * N_TOK + i)) * C_DIM + h * HD + tx;
            g_att[o]      = oacc[ii][0];
            g_att[o + 16] = oacc[ii][1];
        }
    }
}

// ---------------------------------------------------------------
// Launch
// ---------------------------------------------------------------
extern "C" void kernel_launch(void* const* d_in, const int* in_sizes, int n_in,
                              void* d_out, int out_size) {
    const float* x          = (const float*)d_in[0];
    const float* mask       = (const float*)d_in[1];
    const float* qkv_w      = (const float*)d_in[2];
    const float* qkv_b      = (const float*)d_in[3];
    const float* proj_w     = (const float*)d_in[4];
    const float* proj_b     = (const float*)d_in[5];
    const float* bias_table = (const float*)d_in[6];
    const int*   rel_index  = (const int*)d_in[7];
    float* out = (float*)d_out;

    // dynamic smem for the attention kernel (~86.6 KB)
    const int attn_smem = (3 * PADN * QROW + PADN * SROW) * (int)sizeof(float);
    cudaFuncSetAttribute(attn_kernel,
                         cudaFuncAttributeMaxDynamicSharedMemorySize, attn_smem);

    // 1) bias gather
    {
        int total = H_NUM * N_TOK * N_TOK;
        gather_bias_kernel<<<(total + 255) / 256, 256>>>(bias_table, rel_index);
    }
    // 2) QKV projection: [200704,256] x [768,256]^T -> g_qkv
    {
        dim3 grid(QKV_N / 128, M_ROWS / 128);
        qkv_gemm_kernel<<<grid, 256>>>(x, qkv_w, qkv_b);
    }
    // 3) fused attention per (b,h)
    {
        attn_kernel<<<B_TOT * H_NUM, 256, attn_smem>>>(mask);
    }
    // 4) output projection: [200704,256] x [256,256]^T -> d_out
    {
        dim3 grid(C_DIM / 128, M_ROWS / 128);
        proj_gemm_kernel<<<grid, 256>>>(proj_w, proj_b, out);
    }
}

// round 7
// speedup vs baseline: 1.5890x; 1.5890x over previous
#include <cuda_runtime.h>
#include <cuda_bf16.h>
#include <cstdint>

// Problem constants
#define B_TOT   2048
#define N_TOK   98
#define C_DIM   256
#define H_NUM   8
#define HD      32
#define NW      512
#define M_ROWS  (B_TOT * N_TOK)          // 200704
#define QKV_N   (3 * C_DIM)              // 768

// -------- scratch (static device globals: no runtime allocation) --------
// NOTE: referenced ONLY from device code (host-passed shadow addrs read as
// zeros via ATS on GB300 — the silent R3-R6 bug).
__device__ float g_qkv[(size_t)M_ROWS * QKV_N];   // ~616 MB
__device__ float g_att[(size_t)M_ROWS * C_DIM];   // ~205 MB
__device__ float g_bias[H_NUM * N_TOK * N_TOK];

// ================= helpers =================
__device__ __forceinline__ void mma16816(float* c, const uint32_t* a, const uint32_t* b) {
    asm volatile(
        "mma.sync.aligned.m16n8k16.row.col.f32.bf16.bf16.f32 "
        "{%0,%1,%2,%3}, {%4,%5,%6,%7}, {%8,%9}, {%0,%1,%2,%3};"
        : "+f"(c[0]), "+f"(c[1]), "+f"(c[2]), "+f"(c[3])
        : "r"(a[0]), "r"(a[1]), "r"(a[2]), "r"(a[3]), "r"(b[0]), "r"(b[1]));
}

__device__ __forceinline__ void split2(float x, float y, uint32_t& hi, uint32_t& lo) {
    __nv_bfloat16 hx = __float2bfloat16(x);
    __nv_bfloat16 hy = __float2bfloat16(y);
    __nv_bfloat16 lx = __float2bfloat16(x - __bfloat162float(hx));
    __nv_bfloat16 ly = __float2bfloat16(y - __bfloat162float(hy));
    hi = (uint32_t)__bfloat16_as_ushort(hx) | ((uint32_t)__bfloat16_as_ushort(hy) << 16);
    lo = (uint32_t)__bfloat16_as_ushort(lx) | ((uint32_t)__bfloat16_as_ushort(ly) << 16);
}

// ---------------------------------------------------------------
// Kernel 1: gather relative-position bias  -> g_bias[h][n][m]
// ---------------------------------------------------------------
__global__ void gather_bias_kernel(const float* __restrict__ table,
                                   const int* __restrict__ rel) {
    int idx = blockIdx.x * blockDim.x + threadIdx.x;
    const int total = H_NUM * N_TOK * N_TOK;
    if (idx < total) {
        int h  = idx / (N_TOK * N_TOK);
        int nm = idx % (N_TOK * N_TOK);
        g_bias[idx] = table[rel[nm] * H_NUM + h];
    }
}

// ---------------------------------------------------------------
// HMMA bf16x3 split GEMM body: C[m][n] = sum_k A[m][k]*W[n][k] + bias[n]
// CTA: 128x128 tile, BK=32, 8 warps (4x2) of 32x64.
// smem per buffer: A_hi, A_lo, B_hi, B_lo; 128 rows x 32 bf16,
// rows padded to 80 B -> 10240 B per region, 40960 per buffer, x2.
// Fragments via plain 32-bit LDS per documented m16n8k16 maps.
// ---------------------------------------------------------------
#define RB    80          // row bytes (40 halves)
#define REG_B 10240       // region bytes
#define BUF_B 40960       // buffer bytes

__device__ __forceinline__ void ld_chunk(const float* __restrict__ A,
                                         const float* __restrict__ W,
                                         int m0, int n0, int k0, int tid,
                                         float4* r) {
#pragma unroll
    for (int i = 0; i < 4; i++) {
        int f4  = tid + i * 256;
        int row = f4 >> 3;
        int c4  = (f4 & 7) << 2;
        r[i]     = *reinterpret_cast<const float4*>(A + (size_t)(m0 + row) * C_DIM + k0 + c4);
        r[4 + i] = *reinterpret_cast<const float4*>(W + (size_t)(n0 + row) * C_DIM + k0 + c4);
    }
}

__device__ __forceinline__ void st_chunk(char* buf, int tid, const float4* r) {
#pragma unroll
    for (int i = 0; i < 4; i++) {
        int f4  = tid + i * 256;
        int row = f4 >> 3;
        int c4  = (f4 & 7) << 2;
        int off = row * RB + c4 * 2;
        uint32_t h01, l01, h23, l23;
        split2(r[i].x, r[i].y, h01, l01);
        split2(r[i].z, r[i].w, h23, l23);
        *reinterpret_cast<uint2*>(buf + off)         = make_uint2(h01, h23);
        *reinterpret_cast<uint2*>(buf + REG_B + off) = make_uint2(l01, l23);
        split2(r[4 + i].x, r[4 + i].y, h01, l01);
        split2(r[4 + i].z, r[4 + i].w, h23, l23);
        *reinterpret_cast<uint2*>(buf + 2 * REG_B + off) = make_uint2(h01, h23);
        *reinterpret_cast<uint2*>(buf + 3 * REG_B + off) = make_uint2(l01, l23);
    }
}

__device__ __forceinline__ uint32_t lds32(const char* p) {
    return *reinterpret_cast<const uint32_t*>(p);
}

// m16n8k16 fragment maps (g = lane>>2, t = lane&3):
//   a0={A[g][2t,2t+1]} a1={A[g+8][...]} a2={A[g][2t+8,..]} a3={A[g+8][2t+8,..]}
//   b0={B[2t..][g]} b1={B[2t+8..][g]}   (smem B stored [n][k])
//   c0=C[g][2t] c1=C[g][2t+1] c2=C[g+8][2t] c3=C[g+8][2t+1]
__device__ __forceinline__ void compute_chunk(const char* sbuf, int wm, int wn,
                                              int lane, float acc[2][8][4]) {
    const int g = lane >> 2;
    const int t = lane & 3;
#pragma unroll
    for (int ks = 0; ks < 32; ks += 16) {
        uint32_t ah[2][4], al[2][4];
#pragma unroll
        for (int mt = 0; mt < 2; mt++) {
            const char* a0p = sbuf + (wm + mt * 16 + g) * RB + (ks + 2 * t) * 2;
            ah[mt][0] = lds32(a0p);
            ah[mt][1] = lds32(a0p + 8 * RB);
            ah[mt][2] = lds32(a0p + 16);
            ah[mt][3] = lds32(a0p + 8 * RB + 16);
            al[mt][0] = lds32(a0p + REG_B);
            al[mt][1] = lds32(a0p + REG_B + 8 * RB);
            al[mt][2] = lds32(a0p + REG_B + 16);
            al[mt][3] = lds32(a0p + REG_B + 8 * RB + 16);
        }
#pragma unroll
        for (int q = 0; q < 8; q++) {
            const char* b0p = sbuf + 2 * REG_B + (wn + q * 8 + g) * RB + (ks + 2 * t) * 2;
            uint32_t bh[2], bl[2];
            bh[0] = lds32(b0p);
            bh[1] = lds32(b0p + 16);
            bl[0] = lds32(b0p + REG_B);
            bl[1] = lds32(b0p + REG_B + 16);
#pragma unroll
            for (int mt = 0; mt < 2; mt++) {
                mma16816(acc[mt][q], ah[mt], bh);
                mma16816(acc[mt][q], ah[mt], bl);
                mma16816(acc[mt][q], al[mt], bh);
            }
        }
    }
}

__device__ __forceinline__ void hgemm_body(char* smem,
                                           const float* __restrict__ A,
                                           const float* __restrict__ W,
                                           const float* __restrict__ bias,
                                           float* __restrict__ C, int Ntot) {
    const int tid  = threadIdx.x;
    const int wid  = tid >> 5;
    const int lane = tid & 31;
    const int m0 = blockIdx.y * 128;
    const int n0 = blockIdx.x * 128;
    const int wm = (wid >> 1) * 32;
    const int wn = (wid & 1) * 64;

    float acc[2][8][4];
#pragma unroll
    for (int mt = 0; mt < 2; mt++)
#pragma unroll
        for (int nt = 0; nt < 8; nt++)
#pragma unroll
            for (int j = 0; j < 4; j++) acc[mt][nt][j] = 0.f;

    float4 pref[8];
    ld_chunk(A, W, m0, n0, 0, tid, pref);
    st_chunk(smem, tid, pref);
    __syncthreads();

#pragma unroll 1
    for (int ch = 0; ch < 8; ch++) {
        if (ch < 7) ld_chunk(A, W, m0, n0, (ch + 1) * 32, tid, pref);
        compute_chunk(smem + (ch & 1) * BUF_B, wm, wn, lane, acc);
        if (ch < 7) st_chunk(smem + ((ch + 1) & 1) * BUF_B, tid, pref);
        __syncthreads();
    }

    const int g = lane >> 2;
    const int t = lane & 3;
#pragma unroll
    for (int mt = 0; mt < 2; mt++) {
#pragma unroll
        for (int q = 0; q < 8; q++) {
            int rr = m0 + wm + mt * 16 + g;
            int cc = n0 + wn + q * 8 + 2 * t;
            float b0 = bias[cc], b1 = bias[cc + 1];
            float2 v0 = make_float2(acc[mt][q][0] + b0, acc[mt][q][1] + b1);
            float2 v1 = make_float2(acc[mt][q][2] + b0, acc[mt][q][3] + b1);
            *reinterpret_cast<float2*>(C + (size_t)rr * Ntot + cc)       = v0;
            *reinterpret_cast<float2*>(C + (size_t)(rr + 8) * Ntot + cc) = v1;
        }
    }
}

// Wrappers: device-side references to the scratch globals (the fix).
__global__ void __launch_bounds__(256, 2)
qkv_gemm_kernel(const float* __restrict__ x, const float* __restrict__ w,
                const float* __restrict__ b) {
    extern __shared__ char smem[];
    hgemm_body(smem, x, w, b, g_qkv, QKV_N);
}

__global__ void __launch_bounds__(256, 2)
proj_gemm_kernel(const float* __restrict__ w, const float* __restrict__ b,
                 float* __restrict__ out) {
    extern __shared__ char smem[];
    hgemm_body(smem, g_att, w, b, out, C_DIM);
}

// ---------------------------------------------------------------
// Kernel 3: fused attention per (b, h) — float4 fragments + V^T
// ---------------------------------------------------------------
#define QROW  36    // q/k row pitch (floats)
#define VTROW 108   // v^T row pitch
#define SROW  100   // S row pitch
#define PADN  112

__global__ void __launch_bounds__(256, 2)
attn_kernel(const float* __restrict__ mask) {
    extern __shared__ float sm[];
    float* q_s = sm;                        // 112*36
    float* k_s = q_s + PADN * QROW;         // 112*36
    float* vT  = k_s + PADN * QROW;         // 32*108
    float* S   = vT + HD * VTROW;           // 112*100

    const int tid = threadIdx.x;
    const int bh  = blockIdx.x;
    const int b   = bh >> 3;
    const int h   = bh & 7;
    const float scale = 0.17677669529663687f;   // 1/sqrt(32)

    for (int idx = tid; idx < PADN * HD; idx += 256) {
        int n = idx >> 5, d = idx & 31;
        float qv = 0.f, kv = 0.f, vv = 0.f;
        if (n < N_TOK) {
            size_t base = ((size_t)(b * N_TOK + n)) * QKV_N + h * HD + d;
            qv = g_qkv[base] * scale;
            kv = g_qkv[base + C_DIM];
            vv = g_qkv[base + 2 * C_DIM];
        }
        q_s[n * QROW + d] = qv;
        k_s[n * QROW + d] = kv;
        if (n < VTROW) vT[d * VTROW + n] = vv;   // cols 98..107 zero
    }
    __syncthreads();

    const int tx = tid & 15, ty = tid >> 4;

    // ---- S = q k^T (float4 fragments along k) ----
    float acc[7][7];
#pragma unroll
    for (int i = 0; i < 7; i++)
#pragma unroll
        for (int j = 0; j < 7; j++) acc[i][j] = 0.f;

#pragma unroll 1
    for (int kk = 0; kk < HD; kk += 4) {
        float4 aq[7];
#pragma unroll
        for (int ii = 0; ii < 7; ii++)
            aq[ii] = *reinterpret_cast<const float4*>(&q_s[(ty + 16 * ii) * QROW + kk]);
#pragma unroll
        for (int jj = 0; jj < 7; jj++) {
            float4 bk = *reinterpret_cast<const float4*>(&k_s[(tx + 16 * jj) * QROW + kk]);
#pragma unroll
            for (int ii = 0; ii < 7; ii++) {
                acc[ii][jj] += aq[ii].x * bk.x;
                acc[ii][jj] += aq[ii].y * bk.y;
                acc[ii][jj] += aq[ii].z * bk.z;
                acc[ii][jj] += aq[ii].w * bk.w;
            }
        }
    }

    const float* mp = mask + (size_t)(b & (NW - 1)) * (N_TOK * N_TOK);
    const float* bp = g_bias + (size_t)h * (N_TOK * N_TOK);
#pragma unroll
    for (int ii = 0; ii < 7; ii++) {
        int i = ty + 16 * ii;
#pragma unroll
        for (int jj = 0; jj < 7; jj++) {
            int j = tx + 16 * jj;
            if (j < SROW)
                S[i * SROW + j] = (i < N_TOK && j < N_TOK)
                    ? acc[ii][jj] + bp[i * N_TOK + j] + mp[i * N_TOK + j]
                    : 0.f;
        }
    }
    __syncthreads();

    // ---- row softmax ----
    {
        const int lane = tid & 31, wp = tid >> 5;
        for (int i = wp; i < N_TOK; i += 8) {
            float* row = S + i * SROW;
            float m = -1e30f;
            for (int j = lane; j < N_TOK; j += 32) m = fmaxf(m, row[j]);
#pragma unroll
            for (int off = 16; off; off >>= 1)
                m = fmaxf(m, __shfl_xor_sync(0xFFFFFFFFu, m, off));
            float s = 0.f;
            for (int j = lane; j < N_TOK; j += 32) {
                float e = __expf(row[j] - m);
                row[j] = e;
                s += e;
            }
#pragma unroll
            for (int off = 16; off; off >>= 1)
                s += __shfl_xor_sync(0xFFFFFFFFu, s, off);
            float inv = 1.f / s;
            for (int j = lane; j < N_TOK; j += 32) row[j] *= inv;
        }
    }
    __syncthreads();

    // ---- O = P v via V^T (float4 along k) ----
    float oacc[7][2];
#pragma unroll
    for (int i = 0; i < 7; i++) { oacc[i][0] = 0.f; oacc[i][1] = 0.f; }

#pragma unroll 1
    for (int kk = 0; kk < SROW; kk += 4) {
        float4 va = *reinterpret_cast<const float4*>(&vT[tx * VTROW + kk]);
        float4 vb = *reinterpret_cast<const float4*>(&vT[(tx + 16) * VTROW + kk]);
#pragma unroll
        for (int ii = 0; ii < 7; ii++) {
            float4 p = *reinterpret_cast<const float4*>(&S[(ty + 16 * ii) * SROW + kk]);
            oacc[ii][0] += p.x * va.x + p.y * va.y + p.z * va.z + p.w * va.w;
            oacc[ii][1] += p.x * vb.x + p.y * vb.y + p.z * vb.z + p.w * vb.w;
        }
    }

#pragma unroll
    for (int ii = 0; ii < 7; ii++) {
        int i = ty + 16 * ii;
        if (i < N_TOK) {
            size_t o = ((size_t)(b * N_TOK + i)) * C_DIM + h * HD + tx;
            g_att[o]      = oacc[ii][0];
            g_att[o + 16] = oacc[ii][1];
        }
    }
}

// ---------------------------------------------------------------
// Launch
// ---------------------------------------------------------------
extern "C" void kernel_launch(void* const* d_in, const int* in_sizes, int n_in,
                              void* d_out, int out_size) {
    const float* x          = (const float*)d_in[0];
    const float* mask       = (const float*)d_in[1];
    const float* qkv_w      = (const float*)d_in[2];
    const float* qkv_b      = (const float*)d_in[3];
    const float* proj_w     = (const float*)d_in[4];
    const float* proj_b     = (const float*)d_in[5];
    const float* bias_table = (const float*)d_in[6];
    const int*   rel_index  = (const int*)d_in[7];
    float* out = (float*)d_out;

    const int attn_smem = (2 * PADN * QROW + HD * VTROW + PADN * SROW) * (int)sizeof(float); // 90880
    cudaFuncSetAttribute(attn_kernel,
                         cudaFuncAttributeMaxDynamicSharedMemorySize, attn_smem);
    const int gemm_smem = 2 * BUF_B;   // 81920
    cudaFuncSetAttribute(qkv_gemm_kernel,
                         cudaFuncAttributeMaxDynamicSharedMemorySize, gemm_smem);
    cudaFuncSetAttribute(proj_gemm_kernel,
                         cudaFuncAttributeMaxDynamicSharedMemorySize, gemm_smem);

    // 1) bias gather
    {
        int total = H_NUM * N_TOK * N_TOK;
        gather_bias_kernel<<<(total + 255) / 256, 256>>>(bias_table, rel_index);
    }
    // 2) QKV projection (HMMA bf16x3): [200704,256] x [768,256]^T -> g_qkv
    {
        dim3 grid(QKV_N / 128, M_ROWS / 128);
        qkv_gemm_kernel<<<grid, 256, gemm_smem>>>(x, qkv_w, qkv_b);
    }
    // 3) fused attention per (b,h)
    {
        attn_kernel<<<B_TOT * H_NUM, 256, attn_smem>>>(mask);
    }
    // 4) output projection (HMMA bf16x3): [200704,256] x [256,256]^T -> d_out
    {
        dim3 grid(C_DIM / 128, M_ROWS / 128);
        proj_gemm_kernel<<<grid, 256, gemm_smem>>>(proj_w, proj_b, out);
    }
}